// round 4
// baseline (speedup 1.0000x reference)
#include <cuda_runtime.h>
#include <math.h>

#define NB 128      // batch
#define NT 512      // time steps
#define ND 256      // input dim
#define NH 512      // hidden dim
#define NG 2048     // 4*NH
#define NCTA 128    // persistent grid size (<=148 SMs -> all resident)
#define KC 64       // K-chunk for recurrent GEMM
#define HP 132      // smem pitch for transposed h chunk (16B aligned, conflict-reducing)

// -------------------- device scratch (no allocs allowed) --------------------
__device__ float g_zx[(size_t)NT * NB * NG];   // 512 MB precomputed x-projection
__device__ float g_hbuf[2][NB * NH];           // double-buffered hidden state
__device__ unsigned g_bar_count;
__device__ volatile unsigned g_bar_gen;

// -------------------- software grid barrier (all CTAs resident) ------------
__device__ __forceinline__ void grid_barrier() {
    __threadfence();          // make this thread's global stores visible (L2)
    __syncthreads();
    if (threadIdx.x == 0) {
        unsigned gen = g_bar_gen;
        unsigned a = atomicAdd(&g_bar_count, 1u);
        if (a == NCTA - 1) {
            atomicExch(&g_bar_count, 0u);
            __threadfence();
            g_bar_gen = gen + 1;   // release (st.volatile -> L2)
        } else {
            while (g_bar_gen == gen) { __nanosleep(32); }
        }
    }
    __syncthreads();
}

// -------------------- Phase 1: zx[t][b][:] = x[b][t][:] @ Wx + bias --------
// M = T*B (m = t*128 + b), N = 2048, K = 256. Tile 128x64, 256 thr, 8x4 micro.
__global__ void __launch_bounds__(256) zx_gemm(const float* __restrict__ x,
                                               const float* __restrict__ Wx,
                                               const float* __restrict__ bias) {
    __shared__ float shAT[16 * HP];   // [kk][b] transposed A tile (pitch 132)
    __shared__ float shB[16 * 64];    // [kk][j]

    const int nt = blockIdx.x;        // 0..31
    const int mt = blockIdx.y;        // 0..511  (== t, since tile M = 128 = NB)
    const int tid = threadIdx.x;
    const int cg = tid & 15;          // col group -> 4 cols
    const int rg = tid >> 4;          // row group -> 8 rows
    const int c0 = cg << 2;
    const int r0 = rg << 3;

    float acc[8][4];
#pragma unroll
    for (int r = 0; r < 8; ++r)
#pragma unroll
        for (int c = 0; c < 4; ++c) acc[r][c] = 0.f;

    for (int k0 = 0; k0 < ND; k0 += 16) {
        // load A tile: x[b][mt][k0+kk] -> shAT[kk][b]
#pragma unroll
        for (int i = 0; i < 8; ++i) {
            int flat = i * 256 + tid;
            int kk = flat & 15;
            int b = flat >> 4;
            shAT[kk * HP + b] = x[(size_t)b * (NT * ND) + (size_t)mt * ND + k0 + kk];
        }
        // load B tile: Wx[k0+kk][nt*64+j] -> shB[kk][j]
#pragma unroll
        for (int i = 0; i < 4; ++i) {
            int flat = i * 256 + tid;
            int j = flat & 63;
            int kk = flat >> 6;
            shB[kk * 64 + j] = Wx[(size_t)(k0 + kk) * NG + nt * 64 + j];
        }
        __syncthreads();
#pragma unroll
        for (int kk = 0; kk < 16; ++kk) {
            const float4 b4 = *(const float4*)&shB[kk * 64 + c0];
            const float4 a0 = *(const float4*)&shAT[kk * HP + r0];
            const float4 a1 = *(const float4*)&shAT[kk * HP + r0 + 4];
            const float av[8] = {a0.x, a0.y, a0.z, a0.w, a1.x, a1.y, a1.z, a1.w};
            const float bv[4] = {b4.x, b4.y, b4.z, b4.w};
#pragma unroll
            for (int r = 0; r < 8; ++r)
#pragma unroll
                for (int c = 0; c < 4; ++c) acc[r][c] += av[r] * bv[c];
        }
        __syncthreads();
    }

    const float4 bb = *(const float4*)&bias[nt * 64 + c0];
#pragma unroll
    for (int r = 0; r < 8; ++r) {
        size_t m = (size_t)mt * NB + r0 + r;
        float4 v = make_float4(acc[r][0] + bb.x, acc[r][1] + bb.y,
                               acc[r][2] + bb.z, acc[r][3] + bb.w);
        *(float4*)&g_zx[m * NG + nt * 64 + c0] = v;
    }
}

// -------------------- Phase 2: persistent recurrent kernel ------------------
// CTA g owns h-columns [4g, 4g+4) and z-columns {gate*512 + 4g + w}.
// One grid barrier per step (h double-buffered). c lives in registers.
__global__ void __launch_bounds__(256, 1) lstm_persistent(
    const float* __restrict__ Wh, float* __restrict__ out) {
    extern __shared__ float smem[];
    float* sh_wh = smem;                    // [512][16]  = 8192 floats
    float* sh_h  = smem + NH * 16;          // [KC][HP]   = 8448 floats
    float* sh_z  = smem + NH * 16 + KC * HP; // [128][16] = 2048 floats

    const int g = blockIdx.x;    // 0..127
    const int tid = threadIdx.x;

    // Load this CTA's Wh column slice once (reused for all 512 steps).
    for (int i = tid; i < NH * 16; i += 256) {
        int k = i >> 4, c = i & 15;
        int gcol = ((c >> 2) << 9) + (g << 2) + (c & 3);  // gate*512 + 4g + w
        sh_wh[i] = Wh[(size_t)k * NG + gcol];
    }

    const int col = tid & 15;                 // local z-column
    const int rb = (tid >> 4) << 3;           // 8 batch rows per thread
    const int gcol = ((col >> 2) << 9) + (g << 2) + (col & 3);
    const int w = tid & 3;                    // gate-local h-column
    const int hj = (g << 2) + w;              // global h-column owned
    float cst[2] = {0.f, 0.f};                // cell state, 2 cells/thread

    __syncthreads();

    for (int t = 0; t < NT; ++t) {
        float acc[8] = {0.f, 0.f, 0.f, 0.f, 0.f, 0.f, 0.f, 0.f};

        if (t > 0) {
            const float* hbuf = g_hbuf[(t + 1) & 1];   // buffer written at t-1
            for (int k0 = 0; k0 < NH; k0 += KC) {
                __syncthreads();   // sh_h safe to overwrite
#pragma unroll
                for (int i = 0; i < (KC * NB) / 256; ++i) {
                    int flat = i * 256 + tid;
                    int kk = flat & (KC - 1);
                    int b = flat >> 6;
                    sh_h[kk * HP + b] = __ldcg(&hbuf[b * NH + k0 + kk]);
                }
                __syncthreads();
#pragma unroll 8
                for (int kk = 0; kk < KC; ++kk) {
                    const float wv = sh_wh[(k0 + kk) * 16 + col];
                    const float4 h0 = *(const float4*)&sh_h[kk * HP + rb];
                    const float4 h1 = *(const float4*)&sh_h[kk * HP + rb + 4];
                    acc[0] += h0.x * wv; acc[1] += h0.y * wv;
                    acc[2] += h0.z * wv; acc[3] += h0.w * wv;
                    acc[4] += h1.x * wv; acc[5] += h1.y * wv;
                    acc[6] += h1.z * wv; acc[7] += h1.w * wv;
                }
            }
        }

        // z = h@Wh + zx  -> smem
        const float* zxr = g_zx + (size_t)t * NB * NG;
#pragma unroll
        for (int r = 0; r < 8; ++r) {
            int b = rb + r;
            sh_z[b * 16 + col] = acc[r] + zxr[(size_t)b * NG + gcol];
        }
        __syncthreads();

        // gates: 2 cells per thread (b = cell>>2 over 128 rows, fixed w)
        float* hout = g_hbuf[t & 1];
#pragma unroll
        for (int u = 0; u < 2; ++u) {
            int b = (tid + u * 256) >> 2;
            float zi = sh_z[b * 16 + 0 + w];
            float zf = sh_z[b * 16 + 4 + w];
            float zg = sh_z[b * 16 + 8 + w];
            float zo = sh_z[b * 16 + 12 + w];
            float si = 1.f / (1.f + expf(-zi));
            float sf = 1.f / (1.f + expf(-zf));
            float tg = tanhf(zg);
            float so = 1.f / (1.f + expf(-zo));
            float cn = sf * cst[u] + si * tg;
            cst[u] = cn;
            float hn = so * tanhf(cn);
            __stcg(&hout[b * NH + hj], hn);                       // next-step h (L2)
            out[(size_t)b * NT * NH + (size_t)t * NH + hj] = hn;  // outputs[b][t][hj]
            if (t == NT - 1) {
                out[(size_t)NB * NT * NH + (size_t)b * NH + hj] = hn;              // hT
                out[(size_t)NB * NT * NH + (size_t)NB * NH + (size_t)b * NH + hj] = cn; // cT
            }
        }

        if (t < NT - 1) grid_barrier();
    }
}

// -------------------- launch --------------------
extern "C" void kernel_launch(void* const* d_in, const int* in_sizes, int n_in,
                              void* d_out, int out_size) {
    const float* x    = (const float*)d_in[0];  // [B,T,D]
    const float* Wx   = (const float*)d_in[1];  // [D,4H]
    const float* Wh   = (const float*)d_in[2];  // [H,4H]
    const float* bias = (const float*)d_in[3];  // [4H]
    float* out = (float*)d_out;

    dim3 g1(NG / 64, (NT * NB) / 128);          // (32, 512)
    zx_gemm<<<g1, 256>>>(x, Wx, bias);

    const int smem_bytes = (NH * 16 + KC * HP + NB * 16) * (int)sizeof(float); // 74752
    cudaFuncSetAttribute(lstm_persistent,
                         cudaFuncAttributeMaxDynamicSharedMemorySize, smem_bytes);
    lstm_persistent<<<NCTA, 256, smem_bytes>>>(Wh, out);
}

// round 6
// speedup vs baseline: 1.1623x; 1.1623x over previous
#include <cuda_runtime.h>
#include <stdint.h>
#include <math.h>

#define NB 128      // batch
#define NT 512      // time steps
#define ND 256      // input dim
#define NH 512      // hidden dim
#define NG 2048     // 4*NH
#define NCTA 128    // persistent grid size (<=148 SMs -> all resident)
#define KC 64       // K-chunk for recurrent GEMM
#define HP 132      // smem pitch for transposed h chunk (132*4 bytes, 16B aligned)
#define NCHUNK (NH / KC)   // 8

// -------------------- device scratch (no allocs allowed) --------------------
__device__ float g_zx[(size_t)NT * NB * NG];   // 512 MB precomputed x-projection
__device__ float g_hbuf[2][NH * NB];           // TRANSPOSED hidden state: [hj][b]
__device__ unsigned g_bar_count;
__device__ volatile unsigned g_bar_gen;

// -------------------- cp.async helpers --------------------
__device__ __forceinline__ void cpa16(uint32_t dst_smem, const void* src) {
    asm volatile("cp.async.cg.shared.global [%0], [%1], 16;\n"
                 :: "r"(dst_smem), "l"(src));
}
__device__ __forceinline__ void cpa_commit() {
    asm volatile("cp.async.commit_group;\n");
}
__device__ __forceinline__ void cpa_wait1() {
    asm volatile("cp.async.wait_group 1;\n");
}

// -------------------- fast activations (budget: rel_err < 1e-3) ------------
__device__ __forceinline__ float fsigmoid(float x) {
    return 1.f / (1.f + __expf(-x));
}
__device__ __forceinline__ float ftanh(float x) {
    return 1.f - 2.f / (1.f + __expf(2.f * x));
}

// -------------------- software grid barrier (all CTAs resident) ------------
__device__ __forceinline__ void grid_barrier() {
    __threadfence();          // make this thread's global stores visible (L2)
    __syncthreads();
    if (threadIdx.x == 0) {
        unsigned gen = g_bar_gen;
        unsigned a = atomicAdd(&g_bar_count, 1u);
        if (a == NCTA - 1) {
            atomicExch(&g_bar_count, 0u);
            __threadfence();
            g_bar_gen = gen + 1;   // release
        } else {
            while (g_bar_gen == gen) { __nanosleep(32); }
        }
    }
    __syncthreads();
}

// -------------------- Phase 1: zx[t][b][:] = x[b][t][:] @ Wx + bias --------
// M = T*B (m = t*128 + b), N = 2048, K = 256. Tile 128x64, 256 thr, 8x4 micro.
__global__ void __launch_bounds__(256) zx_gemm(const float* __restrict__ x,
                                               const float* __restrict__ Wx,
                                               const float* __restrict__ bias) {
    __shared__ float shAT[16 * HP];   // [kk][b] transposed A tile (pitch 132)
    __shared__ float shB[16 * 64];    // [kk][j]

    const int nt = blockIdx.x;        // 0..31
    const int mt = blockIdx.y;        // 0..511  (== t, since tile M = 128 = NB)
    const int tid = threadIdx.x;
    const int cg = tid & 15;          // col group -> 4 cols
    const int rg = tid >> 4;          // row group -> 8 rows
    const int c0 = cg << 2;
    const int r0 = rg << 3;

    float acc[8][4];
#pragma unroll
    for (int r = 0; r < 8; ++r)
#pragma unroll
        for (int c = 0; c < 4; ++c) acc[r][c] = 0.f;

    for (int k0 = 0; k0 < ND; k0 += 16) {
        // load A tile: x[b][mt][k0+kk] -> shAT[kk][b]
#pragma unroll
        for (int i = 0; i < 8; ++i) {
            int flat = i * 256 + tid;
            int kk = flat & 15;
            int b = flat >> 4;
            shAT[kk * HP + b] = x[(size_t)b * (NT * ND) + (size_t)mt * ND + k0 + kk];
        }
        // load B tile: Wx[k0+kk][nt*64+j] -> shB[kk][j]
#pragma unroll
        for (int i = 0; i < 4; ++i) {
            int flat = i * 256 + tid;
            int j = flat & 63;
            int kk = flat >> 6;
            shB[kk * 64 + j] = Wx[(size_t)(k0 + kk) * NG + nt * 64 + j];
        }
        __syncthreads();
#pragma unroll
        for (int kk = 0; kk < 16; ++kk) {
            const float4 b4 = *(const float4*)&shB[kk * 64 + c0];
            const float4 a0 = *(const float4*)&shAT[kk * HP + r0];
            const float4 a1 = *(const float4*)&shAT[kk * HP + r0 + 4];
            const float av[8] = {a0.x, a0.y, a0.z, a0.w, a1.x, a1.y, a1.z, a1.w};
            const float bv[4] = {b4.x, b4.y, b4.z, b4.w};
#pragma unroll
            for (int r = 0; r < 8; ++r)
#pragma unroll
                for (int c = 0; c < 4; ++c) acc[r][c] += av[r] * bv[c];
        }
        __syncthreads();
    }

    const float4 bb = *(const float4*)&bias[nt * 64 + c0];
#pragma unroll
    for (int r = 0; r < 8; ++r) {
        size_t m = (size_t)mt * NB + r0 + r;
        float4 v = make_float4(acc[r][0] + bb.x, acc[r][1] + bb.y,
                               acc[r][2] + bb.z, acc[r][3] + bb.w);
        *(float4*)&g_zx[m * NG + nt * 64 + c0] = v;
    }
}

// -------------------- Phase 2: persistent recurrent kernel ------------------
// CTA g owns h-columns [4g, 4g+4) and z-columns {gate*512 + 4g + w}.
// One grid barrier per step (h double-buffered globally). c in registers.
// sh_h double-buffered in smem; chunks streamed with cp.async.cg while the
// previous chunk's FFMAs run.
__global__ void __launch_bounds__(256, 1) lstm_persistent(
    const float* __restrict__ Wh, float* __restrict__ out) {
    extern __shared__ float smem[];
    float* sh_wh = smem;                          // [512][16]  = 8192 floats
    float* sh_h  = smem + NH * 16;                // [2][KC][HP] = 16896 floats
    float* sh_z  = smem + NH * 16 + 2 * KC * HP;  // [128][16]  = 2048 floats

    const int g = blockIdx.x;    // 0..127
    const int tid = threadIdx.x;

    // Load this CTA's Wh column slice once (reused for all 512 steps).
    for (int i = tid; i < NH * 16; i += 256) {
        int k = i >> 4, c = i & 15;
        int gcol = ((c >> 2) << 9) + (g << 2) + (c & 3);  // gate*512 + 4g + w
        sh_wh[i] = Wh[(size_t)k * NG + gcol];
    }

    const int col = tid & 15;                 // local z-column
    const int rb = (tid >> 4) << 3;           // 8 batch rows per thread
    const int gcol = ((col >> 2) << 9) + (g << 2) + (col & 3);
    const int w = tid & 3;                    // gate-local h-column
    const int hj = (g << 2) + w;              // global h-column owned
    float cst[2] = {0.f, 0.f};                // cell state, 2 cells/thread

    // Precompute this thread's cp.async smem dst addresses / gmem src offsets.
    // Each chunk = KC*NB floats = 2048 16B-segments; 8 segments per thread.
    // seg s: kk = s >> 5 (32 segs per kk row), b4 = (s & 31) * 4.
    uint32_t cp_dst[8];
    int      cp_src[8];   // offset (floats) within hbuf chunk base
    {
        uint32_t sh_h_base = (uint32_t)__cvta_generic_to_shared(sh_h);
#pragma unroll
        for (int i = 0; i < 8; ++i) {
            int s = i * 256 + tid;
            int kk = s >> 5;
            int b4 = (s & 31) << 2;
            cp_dst[i] = sh_h_base + (uint32_t)(kk * HP + b4) * 4u;
            cp_src[i] = kk * NB + b4;
        }
    }
    const uint32_t buf_bytes = (uint32_t)(KC * HP) * 4u;

    __syncthreads();

    for (int t = 0; t < NT; ++t) {
        // ---- prefetch zx for this step (DRAM latency hidden behind GEMM) ----
        const float* zxr = g_zx + (size_t)t * NB * NG;
        float zxv[8];
#pragma unroll
        for (int r = 0; r < 8; ++r)
            zxv[r] = __ldg(&zxr[(size_t)(rb + r) * NG + gcol]);

        float acc[8] = {0.f, 0.f, 0.f, 0.f, 0.f, 0.f, 0.f, 0.f};

        if (t > 0) {
            const float* hbuf = g_hbuf[(t + 1) & 1];   // [hj][b], written at t-1

            // prologue: stream chunk 0 into buffer 0
#pragma unroll
            for (int i = 0; i < 8; ++i)
                cpa16(cp_dst[i], hbuf + cp_src[i]);
            cpa_commit();

            for (int c = 0; c < NCHUNK; ++c) {
                // stream next chunk into the other buffer (safe: that buffer's
                // last readers finished at the syncthreads ending iter c-1)
                if (c + 1 < NCHUNK) {
                    const float* src = hbuf + (c + 1) * KC * NB;
                    uint32_t dofs = ((c + 1) & 1) ? buf_bytes : 0u;
#pragma unroll
                    for (int i = 0; i < 8; ++i)
                        cpa16(cp_dst[i] + dofs, src + cp_src[i]);
                }
                cpa_commit();            // (empty group on last iter)
                cpa_wait1();             // chunk c resident
                __syncthreads();

                const float* hb = sh_h + ((c & 1) ? KC * HP : 0);
                const float* whk = sh_wh + c * KC * 16;
#pragma unroll 8
                for (int kk = 0; kk < KC; ++kk) {
                    const float wv = whk[kk * 16 + col];
                    const float4 h0 = *(const float4*)&hb[kk * HP + rb];
                    const float4 h1 = *(const float4*)&hb[kk * HP + rb + 4];
                    acc[0] += h0.x * wv; acc[1] += h0.y * wv;
                    acc[2] += h0.z * wv; acc[3] += h0.w * wv;
                    acc[4] += h1.x * wv; acc[5] += h1.y * wv;
                    acc[6] += h1.z * wv; acc[7] += h1.w * wv;
                }
                __syncthreads();         // all reads of this buffer done
            }
        }

        // z = h@Wh + zx  -> smem
#pragma unroll
        for (int r = 0; r < 8; ++r) {
            int b = rb + r;
            sh_z[b * 16 + col] = acc[r] + zxv[r];
        }
        __syncthreads();

        // gates: 2 cells per thread (b = cell>>2 over 128 rows, fixed w)
        float* hout = g_hbuf[t & 1];
#pragma unroll
        for (int u = 0; u < 2; ++u) {
            int b = (tid + u * 256) >> 2;
            float zi = sh_z[b * 16 + 0 + w];
            float zf = sh_z[b * 16 + 4 + w];
            float zg = sh_z[b * 16 + 8 + w];
            float zo = sh_z[b * 16 + 12 + w];
            float si = fsigmoid(zi);
            float sf = fsigmoid(zf);
            float tg = ftanh(zg);
            float so = fsigmoid(zo);
            float cn = sf * cst[u] + si * tg;
            cst[u] = cn;
            float hn = so * ftanh(cn);
            __stcg(&hout[hj * NB + b], hn);                       // transposed h (L2)
            out[(size_t)b * NT * NH + (size_t)t * NH + hj] = hn;  // outputs[b][t][hj]
            if (t == NT - 1) {
                out[(size_t)NB * NT * NH + (size_t)b * NH + hj] = hn;              // hT
                out[(size_t)NB * NT * NH + (size_t)NB * NH + (size_t)b * NH + hj] = cn; // cT
            }
        }

        if (t < NT - 1) grid_barrier();
    }
}

// -------------------- launch --------------------
extern "C" void kernel_launch(void* const* d_in, const int* in_sizes, int n_in,
                              void* d_out, int out_size) {
    const float* x    = (const float*)d_in[0];  // [B,T,D]
    const float* Wx   = (const float*)d_in[1];  // [D,4H]
    const float* Wh   = (const float*)d_in[2];  // [H,4H]
    const float* bias = (const float*)d_in[3];  // [4H]
    float* out = (float*)d_out;

    dim3 g1(NG / 64, (NT * NB) / 128);          // (32, 512)
    zx_gemm<<<g1, 256>>>(x, Wx, bias);

    const int smem_bytes = (NH * 16 + 2 * KC * HP + NB * 16) * (int)sizeof(float); // 108544
    cudaFuncSetAttribute(lstm_persistent,
                         cudaFuncAttributeMaxDynamicSharedMemorySize, smem_bytes);
    lstm_persistent<<<NCTA, 256, smem_bytes>>>(Wh, out);
}

// round 7
// speedup vs baseline: 1.1796x; 1.0149x over previous
#include <cuda_runtime.h>
#include <stdint.h>
#include <math.h>

#define NB 128      // batch
#define NT 512      // time steps
#define ND 256      // input dim
#define NH 512      // hidden dim
#define NG 2048     // 4*NH
#define NCTA 128    // persistent grid size (<=148 SMs -> all resident)
#define KC 64       // K-chunk for recurrent GEMM
#define HP 132      // smem pitch for transposed h chunk
#define NCHUNK (NH / KC)   // 8
#define NGROUP 8           // CTA groups of 16; group G produces h cols [G*64,(G+1)*64)

// -------------------- device scratch (no allocs allowed) --------------------
// zx stored TRANSPOSED: g_zx[t][col][b]  (col = gate*512 + hj)
__device__ float g_zx[(size_t)NT * NG * NB];
__device__ float g_hbuf[2][NH * NB];           // transposed hidden state: [hj][b]
__device__ unsigned g_arrive[NGROUP];          // monotonic per-group arrival counters
__device__ unsigned g_gemm_done;               // monotonic completed-GEMM counter

// -------------------- cp.async helpers --------------------
__device__ __forceinline__ void cpa16(uint32_t dst_smem, const void* src) {
    asm volatile("cp.async.cg.shared.global [%0], [%1], 16;\n"
                 :: "r"(dst_smem), "l"(src));
}
__device__ __forceinline__ void cpa_commit() {
    asm volatile("cp.async.commit_group;\n");
}
__device__ __forceinline__ void cpa_wait0() {
    asm volatile("cp.async.wait_group 0;\n");
}

// -------------------- flag wait (acquire) --------------------
__device__ __forceinline__ void wait_ge(const unsigned* p, unsigned target) {
    unsigned v;
    asm volatile("ld.acquire.gpu.global.u32 %0, [%1];" : "=r"(v) : "l"(p));
    while (v < target) {
        __nanosleep(64);
        asm volatile("ld.acquire.gpu.global.u32 %0, [%1];" : "=r"(v) : "l"(p));
    }
}
__device__ __forceinline__ void red_add(unsigned* p, unsigned v) {
    asm volatile("red.relaxed.gpu.global.add.u32 [%0], %1;" :: "l"(p), "r"(v));
}

// -------------------- fast activations (budget: rel_err < 1e-3) ------------
__device__ __forceinline__ float fsigmoid(float x) {
    return 1.f / (1.f + __expf(-x));
}
__device__ __forceinline__ float ftanh(float x) {
    return 1.f - 2.f / (1.f + __expf(2.f * x));
}

// -------------------- init kernel: reset counters each replay ---------------
__global__ void sync_init() {
    if (threadIdx.x < NGROUP) g_arrive[threadIdx.x] = 0u;
    if (threadIdx.x == NGROUP) g_gemm_done = 0u;
}

// -------------------- Phase 1: zx_t[t][col][b] = (x@Wx + b) transposed ------
// M = T*B, N = 2048, K = 256. Tile 128x64, 256 thr, 8x4 micro.
__global__ void __launch_bounds__(256) zx_gemm(const float* __restrict__ x,
                                               const float* __restrict__ Wx,
                                               const float* __restrict__ bias) {
    __shared__ float shAT[16 * HP];   // [kk][b] transposed A tile
    __shared__ float shB[16 * 64];    // [kk][j]

    const int nt = blockIdx.x;        // 0..31
    const int mt = blockIdx.y;        // 0..511  (== t, tile M = 128 = NB)
    const int tid = threadIdx.x;
    const int cg = tid & 15;
    const int rg = tid >> 4;
    const int c0 = cg << 2;
    const int r0 = rg << 3;

    float acc[8][4];
#pragma unroll
    for (int r = 0; r < 8; ++r)
#pragma unroll
        for (int c = 0; c < 4; ++c) acc[r][c] = 0.f;

    for (int k0 = 0; k0 < ND; k0 += 16) {
#pragma unroll
        for (int i = 0; i < 8; ++i) {
            int flat = i * 256 + tid;
            int kk = flat & 15;
            int b = flat >> 4;
            shAT[kk * HP + b] = x[(size_t)b * (NT * ND) + (size_t)mt * ND + k0 + kk];
        }
#pragma unroll
        for (int i = 0; i < 4; ++i) {
            int flat = i * 256 + tid;
            int j = flat & 63;
            int kk = flat >> 6;
            shB[kk * 64 + j] = Wx[(size_t)(k0 + kk) * NG + nt * 64 + j];
        }
        __syncthreads();
#pragma unroll
        for (int kk = 0; kk < 16; ++kk) {
            const float4 b4 = *(const float4*)&shB[kk * 64 + c0];
            const float4 a0 = *(const float4*)&shAT[kk * HP + r0];
            const float4 a1 = *(const float4*)&shAT[kk * HP + r0 + 4];
            const float av[8] = {a0.x, a0.y, a0.z, a0.w, a1.x, a1.y, a1.z, a1.w};
            const float bv[4] = {b4.x, b4.y, b4.z, b4.w};
#pragma unroll
            for (int r = 0; r < 8; ++r)
#pragma unroll
                for (int c = 0; c < 4; ++c) acc[r][c] += av[r] * bv[c];
        }
        __syncthreads();
    }

    // store transposed: g_zx[(mt*NG + col)*NB + b], contiguous in b
#pragma unroll
    for (int c = 0; c < 4; ++c) {
        const float bc = bias[nt * 64 + c0 + c];
        float4 lo = make_float4(acc[0][c] + bc, acc[1][c] + bc,
                                acc[2][c] + bc, acc[3][c] + bc);
        float4 hi = make_float4(acc[4][c] + bc, acc[5][c] + bc,
                                acc[6][c] + bc, acc[7][c] + bc);
        size_t base = ((size_t)mt * NG + nt * 64 + c0 + c) * NB + r0;
        *(float4*)&g_zx[base] = lo;
        *(float4*)&g_zx[base + 4] = hi;
    }
}

// -------------------- Phase 2: persistent recurrent kernel ------------------
// CTA g owns h-columns [4g, 4g+4) and z-columns {gate*512 + 4g + w}.
// No global barrier: per-group arrival flags consumed chunk-by-chunk inside
// the cp.async pipeline (rotated start = own group). WAR on double-buffered h
// protected by lazy gemm_done counter.
__global__ void __launch_bounds__(256, 1) lstm_persistent(
    const float* __restrict__ Wh, float* __restrict__ out) {
    extern __shared__ float smem[];
    float* sh_wh = smem;                          // [512][16]
    float* sh_h  = smem + NH * 16;                // [2][KC][HP]
    float* sh_z  = smem + NH * 16 + 2 * KC * HP;  // [128][16]

    const int g = blockIdx.x;    // 0..127
    const int tid = threadIdx.x;
    const int grp = g >> 4;      // own producer group

    for (int i = tid; i < NH * 16; i += 256) {
        int k = i >> 4, c = i & 15;
        int gcol = ((c >> 2) << 9) + (g << 2) + (c & 3);  // gate*512 + 4g + w
        sh_wh[i] = Wh[(size_t)k * NG + gcol];
    }

    const int col = tid & 15;
    const int rb = (tid >> 4) << 3;
    const int gcol = ((col >> 2) << 9) + (g << 2) + (col & 3);
    const int w = tid & 3;
    const int hj = (g << 2) + w;
    float cst[2] = {0.f, 0.f};

    uint32_t cp_dst[8];
    int      cp_src[8];
    {
        uint32_t sh_h_base = (uint32_t)__cvta_generic_to_shared(sh_h);
#pragma unroll
        for (int i = 0; i < 8; ++i) {
            int s = i * 256 + tid;
            int kk = s >> 5;
            int b4 = (s & 31) << 2;
            cp_dst[i] = sh_h_base + (uint32_t)(kk * HP + b4) * 4u;
            cp_src[i] = kk * NB + b4;
        }
    }
    const uint32_t buf_bytes = (uint32_t)(KC * HP) * 4u;

    __syncthreads();

    for (int t = 0; t < NT; ++t) {
        // ---- coalesced zx prefetch (hidden behind GEMM) ----
        const float* zxc = g_zx + ((size_t)t * NG + gcol) * NB + rb;
        const float4 z0 = __ldg((const float4*)zxc);
        const float4 z1 = __ldg((const float4*)(zxc + 4));

        float acc[8] = {0.f, 0.f, 0.f, 0.f, 0.f, 0.f, 0.f, 0.f};

        if (t > 0) {
            const float* hbuf = g_hbuf[(t + 1) & 1];   // written at t-1
            const unsigned tgt = 16u * (unsigned)t;

            // prologue: own group first (ready soonest), into buffer 0
            wait_ge(&g_arrive[grp], tgt);
#pragma unroll
            for (int i = 0; i < 8; ++i)
                cpa16(cp_dst[i], hbuf + grp * (KC * NB) + cp_src[i]);
            cpa_commit();

            for (int i = 0; i < NCHUNK; ++i) {
                int cur = grp + i; if (cur >= NCHUNK) cur -= NCHUNK;
                cpa_wait0();             // chunk cur resident
                __syncthreads();         // + all warps done reading other buffer
                if (i < NCHUNK - 1) {
                    int nx = cur + 1; if (nx >= NCHUNK) nx -= NCHUNK;
                    wait_ge(&g_arrive[nx], tgt);
                    const float* src = hbuf + nx * (KC * NB);
                    uint32_t dofs = ((i + 1) & 1) ? buf_bytes : 0u;
#pragma unroll
                    for (int j = 0; j < 8; ++j)
                        cpa16(cp_dst[j] + dofs, src + cp_src[j]);
                    cpa_commit();
                }
                const float* hb = sh_h + ((i & 1) ? KC * HP : 0);
                const float* whk = sh_wh + cur * KC * 16;
#pragma unroll 8
                for (int kk = 0; kk < KC; ++kk) {
                    const float wv = whk[kk * 16 + col];
                    const float4 h0 = *(const float4*)&hb[kk * HP + rb];
                    const float4 h1 = *(const float4*)&hb[kk * HP + rb + 4];
                    acc[0] += h0.x * wv; acc[1] += h0.y * wv;
                    acc[2] += h0.z * wv; acc[3] += h0.w * wv;
                    acc[4] += h1.x * wv; acc[5] += h1.y * wv;
                    acc[6] += h1.z * wv; acc[7] += h1.w * wv;
                }
            }
            __syncthreads();             // all global h reads of step t complete
            if (tid == 0) red_add(&g_gemm_done, 1u);
        }

        // z = h@Wh + zx  -> smem
        sh_z[(rb + 0) * 16 + col] = acc[0] + z0.x;
        sh_z[(rb + 1) * 16 + col] = acc[1] + z0.y;
        sh_z[(rb + 2) * 16 + col] = acc[2] + z0.z;
        sh_z[(rb + 3) * 16 + col] = acc[3] + z0.w;
        sh_z[(rb + 4) * 16 + col] = acc[4] + z1.x;
        sh_z[(rb + 5) * 16 + col] = acc[5] + z1.y;
        sh_z[(rb + 6) * 16 + col] = acc[6] + z1.z;
        sh_z[(rb + 7) * 16 + col] = acc[7] + z1.w;
        __syncthreads();

        // WAR guard: writing hbuf[t&1] requires all step t-1 GEMM reads done
        if (t >= 2) wait_ge(&g_gemm_done, 128u * (unsigned)(t - 1));

        // gates: 2 cells per thread
        float* hout = g_hbuf[t & 1];
#pragma unroll
        for (int u = 0; u < 2; ++u) {
            int b = (tid + u * 256) >> 2;
            float zi = sh_z[b * 16 + 0 + w];
            float zf = sh_z[b * 16 + 4 + w];
            float zg = sh_z[b * 16 + 8 + w];
            float zo = sh_z[b * 16 + 12 + w];
            float si = fsigmoid(zi);
            float sf = fsigmoid(zf);
            float tg = ftanh(zg);
            float so = fsigmoid(zo);
            float cn = sf * cst[u] + si * tg;
            cst[u] = cn;
            float hn = so * ftanh(cn);
            __stcg(&hout[hj * NB + b], hn);                       // transposed h
            out[(size_t)b * NT * NH + (size_t)t * NH + hj] = hn;  // outputs[b][t][hj]
            if (t == NT - 1) {
                out[(size_t)NB * NT * NH + (size_t)b * NH + hj] = hn;              // hT
                out[(size_t)NB * NT * NH + (size_t)NB * NH + (size_t)b * NH + hj] = cn; // cT
            }
        }

        // publish this CTA's h columns for step t
        __threadfence();
        __syncthreads();
        if (tid == 0) red_add(&g_arrive[grp], 1u);
    }
}

// -------------------- launch --------------------
extern "C" void kernel_launch(void* const* d_in, const int* in_sizes, int n_in,
                              void* d_out, int out_size) {
    const float* x    = (const float*)d_in[0];  // [B,T,D]
    const float* Wx   = (const float*)d_in[1];  // [D,4H]
    const float* Wh   = (const float*)d_in[2];  // [H,4H]
    const float* bias = (const float*)d_in[3];  // [4H]
    float* out = (float*)d_out;

    sync_init<<<1, 32>>>();

    dim3 g1(NG / 64, (NT * NB) / 128);          // (32, 512)
    zx_gemm<<<g1, 256>>>(x, Wx, bias);

    const int smem_bytes = (NH * 16 + 2 * KC * HP + NB * 16) * (int)sizeof(float); // 108544
    cudaFuncSetAttribute(lstm_persistent,
                         cudaFuncAttributeMaxDynamicSharedMemorySize, smem_bytes);
    lstm_persistent<<<NCTA, 256, smem_bytes>>>(Wh, out);
}